// round 2
// baseline (speedup 1.0000x reference)
#include <cuda_runtime.h>
#include <stdint.h>

// Problem constants
#define IN_FLAT 1024
#define BATCH   512
#define NEURONS 4096
#define FOCUS   64

// Tiling
#define BCH   32          // batch rows per block
#define NPB   128         // neurons per block
#define TPB   1024        // threads per block (32 warps)
#define NWARP (TPB/32)
#define NPW   (NPB/NWARP) // 4 neurons per warp
#define XSTR  33          // padded smem stride (conflict-free stage + gather)
#define TRS   5           // transpose-buffer pad stride

// Pre-packed (offset, weight) pairs: off = idx * XSTR (word offset into x_sh)
__device__ uint4 g_pairs[NEURONS * (FOCUS/2)];

// ---------------------------------------------------------------------------
// Kernel 1: pack connections_index (+weights) into gather-ready uint4 pairs.
// Handles int64 OR int32 index dtype via a deterministic on-device sniff:
// int64 little-endian values in [0,1024) have all odd 4B words == 0.
// ---------------------------------------------------------------------------
__global__ void pack_pairs(const void* __restrict__ conn_raw,
                           const float* __restrict__ wgt) {
    int i = blockIdx.x * blockDim.x + threadIdx.x;
    if (i >= NEURONS * (FOCUS/2)) return;

    const int* ci32 = (const int*)conn_raw;
    bool is64 = true;
    #pragma unroll
    for (int k = 1; k < 64; k += 2) is64 &= (ci32[k] == 0);

    int n = i >> 5;          // / (FOCUS/2)
    int j = i & 31;
    int base = n * FOCUS + 2 * j;

    int i0, i1;
    if (is64) {
        const long long* ci64 = (const long long*)conn_raw;
        i0 = (int)ci64[base];
        i1 = (int)ci64[base + 1];
    } else {
        i0 = ci32[base];
        i1 = ci32[base + 1];
    }

    uint4 p;
    p.x = (unsigned)(i0 * XSTR);
    p.y = __float_as_uint(wgt[base]);
    p.z = (unsigned)(i1 * XSTR);
    p.w = __float_as_uint(wgt[base + 1]);
    g_pairs[i] = p;
}

// ---------------------------------------------------------------------------
// Kernel 2: main gather-FMA kernel, 32 warps/SM for latency hiding.
//   x_sh[col*33 + b_local] : staged x chunk (conflict-free both directions)
//   pairs                  : read straight from gmem (warp-uniform LDG.128,
//                            L1/L2 resident; frees 65 KB smem for occupancy)
//   tr_sh                  : per-warp output transpose buffer (pad 5)
// ---------------------------------------------------------------------------
constexpr int X_SH_FLOATS  = IN_FLAT * XSTR;            // 33792 floats = 135168 B
constexpr int TR_SH_FLOATS = NWARP * BCH * TRS;         //  5120 floats =  20480 B
constexpr size_t SMEM_BYTES = (size_t)(X_SH_FLOATS + TR_SH_FLOATS) * 4; // 155648

__global__ void __launch_bounds__(TPB, 1)
sparse_mm(const float* __restrict__ x, const float* __restrict__ bias,
          float* __restrict__ out) {
    extern __shared__ float sm[];
    float* x_sh  = sm;
    float* tr_sh = sm + X_SH_FLOATS;

    const int tid  = threadIdx.x;
    const int wid  = tid >> 5;
    const int lane = tid & 31;
    const int n0   = blockIdx.x * NPB;
    const int b0   = blockIdx.y * BCH;

    // ---- stage x[b0:b0+32, :] -> x_sh[c*33 + r]; warp wid owns row wid.
    {
        const int r = wid;                           // 32 warps <-> 32 rows
        const float* row = x + (size_t)(b0 + r) * IN_FLAT;
        #pragma unroll
        for (int it = 0; it < IN_FLAT/32; ++it) {
            int c = it * 32 + lane;                  // coalesced LDG.32
            x_sh[c * XSTR + r] = row[c];             // bank (c+r)&31: conflict-free
        }
    }
    __syncthreads();

    // ---- main loop: warp = 4 neurons x 32 batch lanes
    const int nwb = wid * NPW;
    float* tr = tr_sh + wid * (BCH * TRS);

    #pragma unroll
    for (int nn = 0; nn < NPW; ++nn) {
        const uint4* __restrict__ pp = g_pairs + (size_t)(n0 + nwb + nn) * (FOCUS/2);
        float a0 = 0.f, a1 = 0.f;
        #pragma unroll 8
        for (int j = 0; j < FOCUS/2; ++j) {
            uint4 p = __ldg(pp + j);                               // uniform LDG.128 (L1 hit)
            a0 = fmaf(x_sh[p.x + lane], __uint_as_float(p.y), a0); // conflict-free gather
            a1 = fmaf(x_sh[p.z + lane], __uint_as_float(p.w), a1);
        }
        tr[lane * TRS + nn] = a0 + a1 + __ldg(bias + n0 + nwb + nn);
    }
    __syncwarp();

    // ---- de-scattered output: 16B-contiguous groups per STG pass
    const int j  = lane & 3;       // neuron within warp group
    const int bq = lane >> 2;      // batch sub-row (0..7)
    #pragma unroll
    for (int s = 0; s < 4; ++s) {
        int b = s * 8 + bq;
        out[(size_t)(b0 + b) * NEURONS + (n0 + nwb + j)] = tr[b * TRS + j];
    }
}

// ---------------------------------------------------------------------------
extern "C" void kernel_launch(void* const* d_in, const int* in_sizes, int n_in,
                              void* d_out, int out_size) {
    const float* x    = (const float*)d_in[0];
    const void*  conn = d_in[1];                  // int64 (or int32) indices
    const float* wgt  = (const float*)d_in[2];
    const float* bias = (const float*)d_in[3];
    float* out = (float*)d_out;

    cudaFuncSetAttribute(sparse_mm,
                         cudaFuncAttributeMaxDynamicSharedMemorySize,
                         (int)SMEM_BYTES);

    pack_pairs<<<(NEURONS * (FOCUS/2) + 255) / 256, 256>>>(conn, wgt);

    dim3 grid(NEURONS / NPB, BATCH / BCH);        // 32 x 16 = 512 blocks
    sparse_mm<<<grid, TPB, SMEM_BYTES>>>(x, bias, out);
}

// round 3
// speedup vs baseline: 1.2482x; 1.2482x over previous
#include <cuda_runtime.h>
#include <stdint.h>

// Problem constants
#define IN_FLAT 1024
#define BATCH   512
#define NEURONS 4096
#define FOCUS   64

// Tiling
#define BCH   32          // batch rows per block
#define NPB   128         // neurons per block
#define TPB   1024        // threads per block (32 warps)
#define NWARP (TPB/32)
#define NPW   (NPB/NWARP) // 4 neurons per warp
#define XSTR  33          // padded smem stride (conflict-free stage + gather)
#define TRS   5           // transpose-buffer pad stride

// Pre-packed (offset, weight) pairs: off = idx * XSTR (word offset into x_sh)
__device__ uint4 g_pairs[NEURONS * (FOCUS/2)];

// ---------------------------------------------------------------------------
// Kernel 1: pack connections_index (+weights) into gather-ready uint4 pairs.
// Handles int64 OR int32 index dtype via a deterministic on-device sniff:
// int64 little-endian values in [0,1024) have all odd 4B words == 0.
// ---------------------------------------------------------------------------
__global__ void pack_pairs(const void* __restrict__ conn_raw,
                           const float* __restrict__ wgt) {
    int i = blockIdx.x * blockDim.x + threadIdx.x;
    if (i >= NEURONS * (FOCUS/2)) return;

    const int* ci32 = (const int*)conn_raw;
    bool is64 = true;
    #pragma unroll
    for (int k = 1; k < 64; k += 2) is64 &= (ci32[k] == 0);

    int n = i >> 5;          // / (FOCUS/2)
    int j = i & 31;
    int base = n * FOCUS + 2 * j;

    int i0, i1;
    if (is64) {
        const long long* ci64 = (const long long*)conn_raw;
        i0 = (int)ci64[base];
        i1 = (int)ci64[base + 1];
    } else {
        i0 = ci32[base];
        i1 = ci32[base + 1];
    }

    uint4 p;
    p.x = (unsigned)(i0 * XSTR);
    p.y = __float_as_uint(wgt[base]);
    p.z = (unsigned)(i1 * XSTR);
    p.w = __float_as_uint(wgt[base + 1]);
    g_pairs[i] = p;
}

// ---------------------------------------------------------------------------
// Kernel 2: main gather-FMA kernel.
// R1 memory layout (pairs in smem, LDS-only inner loop) x R2 occupancy
// (one 1024-thread block = 32 warps resident, 8 per SMSP).
//   x_sh[col*33 + b_local] : staged x chunk (conflict-free both directions)
//   pr_sh                  : block's pair table (broadcast LDS.128)
//   tr_sh                  : per-warp output transpose buffer (pad 5)
// ---------------------------------------------------------------------------
constexpr int X_SH_FLOATS  = IN_FLAT * XSTR;        // 33792 floats = 135168 B
constexpr int PR_SH_ELEMS  = NPB * (FOCUS/2);       // 4096 uint4   =  65536 B
constexpr int TR_SH_FLOATS = NWARP * BCH * TRS;     // 5120 floats  =  20480 B
constexpr size_t SMEM_BYTES =
    (size_t)X_SH_FLOATS*4 + (size_t)PR_SH_ELEMS*16 + (size_t)TR_SH_FLOATS*4; // 221184

__global__ void __launch_bounds__(TPB, 1)
sparse_mm(const float* __restrict__ x, const float* __restrict__ bias,
          float* __restrict__ out) {
    extern __shared__ float sm[];
    float* x_sh  = sm;
    uint4* pr_sh = (uint4*)(sm + X_SH_FLOATS);
    float* tr_sh = (float*)(pr_sh + PR_SH_ELEMS);

    const int tid  = threadIdx.x;
    const int wid  = tid >> 5;
    const int lane = tid & 31;
    const int n0   = blockIdx.x * NPB;
    const int b0   = blockIdx.y * BCH;

    // ---- stage x[b0:b0+32, :] -> x_sh[c*33 + r]; warp wid owns row wid.
    {
        const int r = wid;                           // 32 warps <-> 32 rows
        const float* row = x + (size_t)(b0 + r) * IN_FLAT;
        #pragma unroll
        for (int it = 0; it < IN_FLAT/32; ++it) {
            int c = it * 32 + lane;                  // coalesced LDG.32, high MLP
            x_sh[c * XSTR + r] = row[c];             // bank (c+r)&31: conflict-free
        }
    }

    // ---- stage this block's pair table (coalesced LDG.128 -> STS.128)
    const uint4* pg = g_pairs + (size_t)n0 * (FOCUS/2);
    #pragma unroll
    for (int i = 0; i < PR_SH_ELEMS / TPB; ++i)      // 4 iterations exactly
        pr_sh[i * TPB + tid] = pg[i * TPB + tid];

    __syncthreads();

    // ---- main loop: warp = 4 neurons x 32 batch lanes, LDS-only
    const int nwb = wid * NPW;
    float* tr = tr_sh + wid * (BCH * TRS);

    #pragma unroll
    for (int nn = 0; nn < NPW; ++nn) {
        const uint4* pp = pr_sh + (nwb + nn) * (FOCUS/2);
        float a0 = 0.f, a1 = 0.f;
        #pragma unroll 8
        for (int j = 0; j < FOCUS/2; ++j) {
            uint4 p = pp[j];                                        // broadcast LDS.128
            a0 = fmaf(x_sh[p.x + lane], __uint_as_float(p.y), a0);  // conflict-free gather
            a1 = fmaf(x_sh[p.z + lane], __uint_as_float(p.w), a1);
        }
        tr[lane * TRS + nn] = a0 + a1 + __ldg(bias + n0 + nwb + nn);
    }
    __syncwarp();

    // ---- de-scattered output: 16B-contiguous groups per STG pass
    const int j  = lane & 3;       // neuron within warp group
    const int bq = lane >> 2;      // batch sub-row (0..7)
    #pragma unroll
    for (int s = 0; s < 4; ++s) {
        int b = s * 8 + bq;
        out[(size_t)(b0 + b) * NEURONS + (n0 + nwb + j)] = tr[b * TRS + j];
    }
}

// ---------------------------------------------------------------------------
extern "C" void kernel_launch(void* const* d_in, const int* in_sizes, int n_in,
                              void* d_out, int out_size) {
    const float* x    = (const float*)d_in[0];
    const void*  conn = d_in[1];                  // int64 (or int32) indices
    const float* wgt  = (const float*)d_in[2];
    const float* bias = (const float*)d_in[3];
    float* out = (float*)d_out;

    cudaFuncSetAttribute(sparse_mm,
                         cudaFuncAttributeMaxDynamicSharedMemorySize,
                         (int)SMEM_BYTES);

    pack_pairs<<<(NEURONS * (FOCUS/2) + 255) / 256, 256>>>(conn, wgt);

    dim3 grid(NEURONS / NPB, BATCH / BCH);        // 32 x 16 = 512 blocks
    sparse_mm<<<grid, TPB, SMEM_BYTES>>>(x, bias, out);
}